// round 1
// baseline (speedup 1.0000x reference)
#include <cuda_runtime.h>
#include <math.h>
#include <stdint.h>

#define NF 2177      // full node count
#define NM 2176      // minor size (NM = NF-1), 68*32
#define NMAT 8       // 4 batches x {z, target}
#define NSTEPS (NM/32)   // 68
#define ROWTILES 17      // 17 * 128 = 2176

// scratch (allocation-free contract: __device__ globals)
__device__ float g_A[NMAT][(size_t)NM * NM];          // ~151.5 MB
__device__ float g_part[NMAT][ROWTILES][NM];          // colsum partials
__device__ float g_logparts[NMAT][NSTEPS];            // per-step sum of log(pivot)

// ---------------------------------------------------------------------------
// Build off-diagonal: A[i][j] = -w(r=i+1, c=j+1)
// ---------------------------------------------------------------------------
__global__ void build_offdiag(const float* __restrict__ scores,
                              const float* __restrict__ tmask,
                              const float* __restrict__ zmask,
                              const int* __restrict__ lengths) {
    size_t idx = (size_t)blockIdx.x * blockDim.x + threadIdx.x;
    const size_t total = (size_t)NMAT * NM * NM;
    if (idx >= total) return;
    int j = (int)(idx % NM);
    size_t t = idx / NM;
    int i = (int)(t % NM);
    int m = (int)(t / NM);
    int b = m >> 1;
    const float* mask = (m & 1) ? tmask : zmask;
    int len = lengths[b];
    int r = i + 1, c = j + 1;
    float w = 0.0f;
    if (r < len && c < len) {
        size_t off = (size_t)b * NF * NF + (size_t)r * NF + c;
        float mk = mask[off];
        if (mk != 0.0f) w = expf(scores[off]) * mk;
    }
    g_A[m][(size_t)i * NM + j] = -w;
}

// ---------------------------------------------------------------------------
// Column sums (deterministic two-stage, no atomics)
// ---------------------------------------------------------------------------
__global__ void colsum_part() {
    int m = blockIdx.z;
    int j = blockIdx.x * 32 + threadIdx.x;
    int i0 = blockIdx.y * 128;
    const float* A = g_A[m];
    float s = 0.0f;
    int ibase = i0 + threadIdx.y * 16;
    #pragma unroll
    for (int rr = 0; rr < 16; rr++) {
        s += A[(size_t)(ibase + rr) * NM + j];
    }
    __shared__ float sh[8][32];
    sh[threadIdx.y][threadIdx.x] = s;
    __syncthreads();
    if (threadIdx.y == 0) {
        float tot = 0.0f;
        #pragma unroll
        for (int y = 0; y < 8; y++) tot += sh[y][threadIdx.x];
        g_part[m][blockIdx.y][j] = tot;
    }
}

__global__ void set_diag(const float* __restrict__ scores,
                         const float* __restrict__ tmask,
                         const float* __restrict__ zmask,
                         const int* __restrict__ lengths) {
    int m = blockIdx.y;
    int j = blockIdx.x * 256 + threadIdx.x;
    if (j >= NM) return;
    float s = 0.0f;
    #pragma unroll
    for (int t = 0; t < ROWTILES; t++) s += g_part[m][t][j];
    float colsum = -s;   // partials summed -w
    int b = m >> 1;
    int len = lengths[b];
    int c = j + 1;
    const float* mask = (m & 1) ? tmask : zmask;
    float diag;
    if (c < len) {
        size_t off = (size_t)b * NF * NF + c;   // row 0 (root) entry
        float w0 = expf(scores[off]) * mask[off];
        diag = colsum + w0;
    } else {
        diag = 1.0f;    // pad identity for invalid suffix
    }
    g_A[m][(size_t)j * NM + j] = diag;
}

// ---------------------------------------------------------------------------
// LU of 32x32 diagonal block, no pivoting (valid: column-dd M-matrix).
// One warp per matrix. Also records sum of log(pivot) for this step.
// ---------------------------------------------------------------------------
__global__ void lu_diag(int k) {
    int m = blockIdx.x;
    int t = threadIdx.x;  // 0..31, owns row t
    __shared__ float s[32][33];
    float* A = g_A[m];
    #pragma unroll 8
    for (int q = 0; q < 32; q++)
        s[t][q] = A[(size_t)(k + t) * NM + (k + q)];
    __syncwarp();
    for (int p = 0; p < 32; p++) {
        float piv = s[p][p];
        if (t > p) {
            float l = s[t][p] / piv;
            s[t][p] = l;
            for (int q = p + 1; q < 32; q++)
                s[t][q] -= l * s[p][q];
        }
        __syncwarp();
    }
    #pragma unroll 8
    for (int q = 0; q < 32; q++)
        A[(size_t)(k + t) * NM + (k + q)] = s[t][q];
    float lg = logf(s[t][t]);
    #pragma unroll
    for (int o = 16; o; o >>= 1) lg += __shfl_xor_sync(0xffffffffu, lg, o);
    if (t == 0) g_logparts[m][k >> 5] = lg;
}

// ---------------------------------------------------------------------------
// L21 = A21 * U11^{-1}  (row-parallel, one row per thread, fully unrolled)
// ---------------------------------------------------------------------------
__global__ void trsm_right(int k, int rem) {
    int m = blockIdx.y;
    float* A = g_A[m];
    __shared__ float u[32][33];
    __shared__ float invd[32];
    for (int e = threadIdx.x; e < 1024; e += blockDim.x) {
        int p = e >> 5, q = e & 31;
        u[p][q] = A[(size_t)(k + p) * NM + (k + q)];
    }
    __syncthreads();
    if (threadIdx.x < 32) invd[threadIdx.x] = 1.0f / u[threadIdx.x][threadIdx.x];
    __syncthreads();

    int row = k + 32 + blockIdx.x * blockDim.x + threadIdx.x;
    if (row >= k + 32 + rem) return;

    float a[32];
    const float4* ld = (const float4*)(A + (size_t)row * NM + k);
    #pragma unroll
    for (int v = 0; v < 8; v++) {
        float4 f = ld[v];
        a[4*v+0] = f.x; a[4*v+1] = f.y; a[4*v+2] = f.z; a[4*v+3] = f.w;
    }
    #pragma unroll
    for (int j = 0; j < 32; j++) {
        float x = a[j];
        #pragma unroll
        for (int p = 0; p < j; p++) x -= a[p] * u[p][j];
        a[j] = x * invd[j];
    }
    float4* st = (float4*)(A + (size_t)row * NM + k);
    #pragma unroll
    for (int v = 0; v < 8; v++) {
        float4 f = make_float4(a[4*v+0], a[4*v+1], a[4*v+2], a[4*v+3]);
        st[v] = f;
    }
}

// ---------------------------------------------------------------------------
// U12 = L11^{-1} * A12  (column-parallel, one column per thread, coalesced)
// ---------------------------------------------------------------------------
__global__ void trsm_left(int k, int rem) {
    int m = blockIdx.y;
    float* A = g_A[m];
    __shared__ float lm[32][33];
    for (int e = threadIdx.x; e < 1024; e += blockDim.x) {
        int p = e >> 5, q = e & 31;
        lm[p][q] = A[(size_t)(k + p) * NM + (k + q)];
    }
    __syncthreads();
    int c = k + 32 + blockIdx.x * blockDim.x + threadIdx.x;
    if (c >= k + 32 + rem) return;
    float x[32];
    #pragma unroll
    for (int p = 0; p < 32; p++) {
        float v = A[(size_t)(k + p) * NM + c];
        #pragma unroll
        for (int q = 0; q < p; q++) v -= lm[p][q] * x[q];
        x[p] = v;
        A[(size_t)(k + p) * NM + c] = v;
    }
}

// ---------------------------------------------------------------------------
// Schur update: C[k+32.., k+32..] -= L21 * U12   (K = 32)
// 64x64 tile / block, 256 threads, 4x4 per thread
// ---------------------------------------------------------------------------
__global__ void schur_gemm(int k, int rem) {
    int m = blockIdx.z;
    float* A = g_A[m];
    const int base = k + 32;
    const int lim = base + rem;      // == NM
    int row0 = base + blockIdx.y * 64;
    int col0 = base + blockIdx.x * 64;

    __shared__ float as[32][68];   // as[p][i] = L21[row0+i][k+p]
    __shared__ float bs[32][68];   // bs[p][j] = U12[k+p][col0+j]

    int tid = threadIdx.x;
    {
        int q = tid & 31;
        int y = tid >> 5;
        #pragma unroll
        for (int rr = 0; rr < 8; rr++) {
            int i = y + (rr << 3);
            int r = row0 + i;
            float v = (r < lim) ? A[(size_t)r * NM + k + q] : 0.0f;
            as[q][i] = v;
        }
    }
    {
        int j = tid & 63;
        int pb = tid >> 6;
        #pragma unroll
        for (int rr = 0; rr < 8; rr++) {
            int p = pb + (rr << 2);
            int cc = col0 + j;
            float v = (cc < lim) ? A[(size_t)(k + p) * NM + cc] : 0.0f;
            bs[p][j] = v;
        }
    }
    __syncthreads();

    int tx = tid & 15, ty = tid >> 4;
    float acc[4][4] = {};
    #pragma unroll
    for (int p = 0; p < 32; p++) {
        float4 av = *(const float4*)&as[p][ty * 4];
        float4 bv = *(const float4*)&bs[p][tx * 4];
        float a0[4] = {av.x, av.y, av.z, av.w};
        float b0[4] = {bv.x, bv.y, bv.z, bv.w};
        #pragma unroll
        for (int ii = 0; ii < 4; ii++)
            #pragma unroll
            for (int jj = 0; jj < 4; jj++)
                acc[ii][jj] += a0[ii] * b0[jj];
    }

    int cb = col0 + tx * 4;
    #pragma unroll
    for (int ii = 0; ii < 4; ii++) {
        int r = row0 + ty * 4 + ii;
        if (r >= lim) continue;
        float* cp = A + (size_t)r * NM + cb;
        if (cb + 3 < lim) {
            float4 v = *(float4*)cp;
            v.x -= acc[ii][0]; v.y -= acc[ii][1];
            v.z -= acc[ii][2]; v.w -= acc[ii][3];
            *(float4*)cp = v;
        } else {
            #pragma unroll
            for (int jj = 0; jj < 4; jj++)
                if (cb + jj < lim) cp[jj] -= acc[ii][jj];
        }
    }
}

// ---------------------------------------------------------------------------
// Finalize: mean over batch of (logdet_z - logdet_t), double accumulation
// ---------------------------------------------------------------------------
__global__ void finalize(float* out) {
    double acc = 0.0;
    for (int b = 0; b < 4; b++) {
        double z = 0.0, t = 0.0;
        for (int s = 0; s < NSTEPS; s++) {
            z += (double)g_logparts[2 * b][s];
            t += (double)g_logparts[2 * b + 1][s];
        }
        acc += (z - t);
    }
    out[0] = (float)(acc * 0.25);
}

// ---------------------------------------------------------------------------
extern "C" void kernel_launch(void* const* d_in, const int* in_sizes, int n_in,
                              void* d_out, int out_size) {
    const float* scores = (const float*)d_in[0];
    const float* tmask  = (const float*)d_in[1];
    const float* zmask  = (const float*)d_in[2];
    const int*   lengths = (const int*)d_in[3];

    const size_t total = (size_t)NMAT * NM * NM;
    build_offdiag<<<(unsigned)((total + 255) / 256), 256>>>(scores, tmask, zmask, lengths);
    colsum_part<<<dim3(NM / 32, ROWTILES, NMAT), dim3(32, 8)>>>();
    set_diag<<<dim3((NM + 255) / 256, NMAT), 256>>>(scores, tmask, zmask, lengths);

    for (int k = 0; k < NM; k += 32) {
        lu_diag<<<NMAT, 32>>>(k);
        int rem = NM - k - 32;
        if (rem > 0) {
            trsm_right<<<dim3((rem + 127) / 128, NMAT), 128>>>(k, rem);
            trsm_left<<<dim3((rem + 255) / 256, NMAT), 256>>>(k, rem);
            int tiles = (rem + 63) / 64;
            schur_gemm<<<dim3(tiles, tiles, NMAT), 256>>>(k, rem);
        }
    }
    finalize<<<1, 1>>>((float*)d_out);
}